// round 3
// baseline (speedup 1.0000x reference)
#include <cuda_runtime.h>
#include <cuda_bf16.h>

#define NBLOCKS 1184
#define NTHREADS 256

// Per-block partials: every slot is written each run -> no init kernel needed.
__device__ float g_p_iou[NBLOCKS];
__device__ float g_p_mse[NBLOCKS];
__device__ unsigned int g_p_nc[NBLOCKS];
__device__ unsigned int g_p_ni[NBLOCKS];
// Ticket counter: statically 0; the last block resets it to 0 -> graph-replay safe.
__device__ unsigned int g_ticket = 0;

struct Acc {
    float iou, mse;
    unsigned int nc, ni;
};

__device__ __forceinline__ void process_box(const float4 p, const float4 g, Acc& a) {
    // gt corners (cx,cy,w,h -> xyxy)
    const float x_min_t = g.x - g.z * 0.5f;
    const float x_max_t = g.x + g.z * 0.5f;
    const float y_min_t = g.y - g.w * 0.5f;
    const float y_max_t = g.y + g.w * 0.5f;
    // pred corners clipped to [0,1]
    const float x_min_p = fmaxf(p.x - p.z * 0.5f, 0.0f);
    const float x_max_p = fminf(p.x + p.z * 0.5f, 1.0f);
    const float y_min_p = fmaxf(p.y - p.w * 0.5f, 0.0f);
    const float y_max_p = fminf(p.y + p.w * 0.5f, 1.0f);
    // overlap
    const float o0 = fmaxf(x_min_t, x_min_p);
    const float o1 = fmaxf(y_min_t, y_min_p);
    const float o2 = fminf(x_max_t, x_max_p);
    const float o3 = fminf(y_max_t, y_max_p);

    const bool inc = (o2 < o0) || (o3 < o1);

    const float dx = p.x - g.x;
    const float dy = p.y - g.y;
    const float dz = p.z - g.z;
    const float dw = p.w - g.w;
    const float sq = dx * dx + dy * dy + dz * dz + dw * dw;

    const float inter = (o2 - o0) * (o3 - o1);
    const float area_p = p.z * p.w;
    const float area_g = g.z * g.w;
    const float iou = __fdividef(inter, area_p + area_g - inter + 1e-7f);

    if (inc) {
        a.ni++;
        a.mse += sq;
    } else {
        a.nc++;
        a.iou += iou;
    }
}

__global__ void __launch_bounds__(NTHREADS) iou_dots_fused(
    const float4* __restrict__ pr,
    const float4* __restrict__ gt,
    float* __restrict__ out,
    int n)
{
    Acc a = {0.0f, 0.0f, 0u, 0u};

    const int stride = gridDim.x * blockDim.x;
    int i = blockIdx.x * blockDim.x + threadIdx.x;

    // Unrolled x4 for MLP: hoist all 8 LDG.128 ahead of compute.
    for (; i + 3 * stride < n; i += 4 * stride) {
        const float4 p0 = __ldcs(pr + i);
        const float4 g0 = __ldcs(gt + i);
        const float4 p1 = __ldcs(pr + i + stride);
        const float4 g1 = __ldcs(gt + i + stride);
        const float4 p2 = __ldcs(pr + i + 2 * stride);
        const float4 g2 = __ldcs(gt + i + 2 * stride);
        const float4 p3 = __ldcs(pr + i + 3 * stride);
        const float4 g3 = __ldcs(gt + i + 3 * stride);
        process_box(p0, g0, a);
        process_box(p1, g1, a);
        process_box(p2, g2, a);
        process_box(p3, g3, a);
    }
    for (; i < n; i += stride) {
        process_box(__ldcs(pr + i), __ldcs(gt + i), a);
    }

    // intra-warp reduce
    #pragma unroll
    for (int off = 16; off > 0; off >>= 1) {
        a.iou += __shfl_down_sync(0xFFFFFFFFu, a.iou, off);
        a.mse += __shfl_down_sync(0xFFFFFFFFu, a.mse, off);
        a.nc  += __shfl_down_sync(0xFFFFFFFFu, a.nc, off);
        a.ni  += __shfl_down_sync(0xFFFFFFFFu, a.ni, off);
    }

    __shared__ float s_iou[8];
    __shared__ float s_mse[8];
    __shared__ unsigned int s_nc[8];
    __shared__ unsigned int s_ni[8];
    __shared__ bool s_last;
    const int wid = threadIdx.x >> 5;
    const int lid = threadIdx.x & 31;
    if (lid == 0) {
        s_iou[wid] = a.iou;
        s_mse[wid] = a.mse;
        s_nc[wid] = a.nc;
        s_ni[wid] = a.ni;
    }
    __syncthreads();
    if (threadIdx.x == 0) {
        float biou = 0.0f, bmse = 0.0f;
        unsigned int bnc = 0u, bni = 0u;
        #pragma unroll
        for (int w = 0; w < NTHREADS / 32; w++) {
            biou += s_iou[w];
            bmse += s_mse[w];
            bnc += s_nc[w];
            bni += s_ni[w];
        }
        g_p_iou[blockIdx.x] = biou;
        g_p_mse[blockIdx.x] = bmse;
        g_p_nc[blockIdx.x] = bnc;
        g_p_ni[blockIdx.x] = bni;
        __threadfence();
        const unsigned int old = atomicAdd(&g_ticket, 1u);
        s_last = (old == gridDim.x - 1u);
    }
    __syncthreads();

    if (s_last) {
        // Last block: reduce all per-block partials and finalize.
        double diou = 0.0, dmse = 0.0;
        unsigned long long dnc = 0ull, dni = 0ull;
        for (int b = threadIdx.x; b < (int)gridDim.x; b += NTHREADS) {
            diou += (double)g_p_iou[b];
            dmse += (double)g_p_mse[b];
            dnc += (unsigned long long)g_p_nc[b];
            dni += (unsigned long long)g_p_ni[b];
        }
        #pragma unroll
        for (int off = 16; off > 0; off >>= 1) {
            diou += __shfl_down_sync(0xFFFFFFFFu, diou, off);
            dmse += __shfl_down_sync(0xFFFFFFFFu, dmse, off);
            dnc  += __shfl_down_sync(0xFFFFFFFFu, dnc, off);
            dni  += __shfl_down_sync(0xFFFFFFFFu, dni, off);
        }
        __shared__ double f_iou[8];
        __shared__ double f_mse[8];
        __shared__ unsigned long long f_nc[8];
        __shared__ unsigned long long f_ni[8];
        if (lid == 0) {
            f_iou[wid] = diou;
            f_mse[wid] = dmse;
            f_nc[wid] = dnc;
            f_ni[wid] = dni;
        }
        __syncthreads();
        if (threadIdx.x == 0) {
            double tiou = 0.0, tmse = 0.0;
            unsigned long long tnc = 0ull, tni = 0ull;
            #pragma unroll
            for (int w = 0; w < NTHREADS / 32; w++) {
                tiou += f_iou[w];
                tmse += f_mse[w];
                tnc += f_nc[w];
                tni += f_ni[w];
            }
            const double mse_denom = (double)((tni * 4ull > 0ull) ? tni * 4ull : 1ull);
            const double iou_denom = (double)((tnc > 0ull) ? tnc : 1ull);
            const float mse_mean = (float)(tmse / mse_denom);
            const float iou_mean = (float)(tiou / iou_denom);
            float res_full = iou_mean + ((tni > 0ull) ? -mse_mean : 0.0f);
            out[0] = (tnc > 0ull) ? res_full : -mse_mean;
            g_ticket = 0u;  // reset for next graph replay
        }
    }
}

extern "C" void kernel_launch(void* const* d_in, const int* in_sizes, int n_in,
                              void* d_out, int out_size) {
    const float4* pr = (const float4*)d_in[0];
    const float4* gt = (const float4*)d_in[1];
    float* out = (float*)d_out;
    const int n = in_sizes[0] / 4;

    iou_dots_fused<<<NBLOCKS, NTHREADS>>>(pr, gt, out, n);
}

// round 7
// speedup vs baseline: 1.1457x; 1.1457x over previous
#include <cuda_runtime.h>
#include <cuda_bf16.h>

#define NBLOCKS 2368
#define NTHREADS 256

// Per-block partials: every slot written each run -> no init kernel needed.
__device__ float g_p_iou[NBLOCKS];
__device__ float g_p_mse[NBLOCKS];
__device__ unsigned int g_p_ni[NBLOCKS];
// Ticket counter: statically 0; last block resets it -> graph-replay safe.
__device__ unsigned int g_ticket = 0;

__global__ void __launch_bounds__(NTHREADS) iou_dots_fused(
    const float4* __restrict__ pr,
    const float4* __restrict__ gt,
    float* __restrict__ out,
    int n)
{
    float iou_sum = 0.0f;
    float mse_sum = 0.0f;
    unsigned int n_inc = 0u;

    const int stride = gridDim.x * blockDim.x;
    for (int i = blockIdx.x * blockDim.x + threadIdx.x; i < n; i += stride) {
        const float4 p = pr[i];
        const float4 g = gt[i];

        // gt corners (cx,cy,w,h -> xyxy)
        const float x_min_t = g.x - g.z * 0.5f;
        const float x_max_t = g.x + g.z * 0.5f;
        const float y_min_t = g.y - g.w * 0.5f;
        const float y_max_t = g.y + g.w * 0.5f;
        // pred corners clipped to [0,1]
        const float x_min_p = fmaxf(p.x - p.z * 0.5f, 0.0f);
        const float x_max_p = fminf(p.x + p.z * 0.5f, 1.0f);
        const float y_min_p = fmaxf(p.y - p.w * 0.5f, 0.0f);
        const float y_max_p = fminf(p.y + p.w * 0.5f, 1.0f);
        // overlap box
        const float o0 = fmaxf(x_min_t, x_min_p);
        const float o1 = fmaxf(y_min_t, y_min_p);
        const float o2 = fminf(x_max_t, x_max_p);
        const float o3 = fminf(y_max_t, y_max_p);

        const bool inc = (o2 < o0) || (o3 < o1);

        if (inc) {
            n_inc++;
            const float dx = p.x - g.x;
            const float dy = p.y - g.y;
            const float dz = p.z - g.z;
            const float dw = p.w - g.w;
            mse_sum += dx * dx + dy * dy + dz * dz + dw * dw;
        } else {
            const float inter = (o2 - o0) * (o3 - o1);
            const float area_p = p.z * p.w;
            const float area_g = g.z * g.w;
            iou_sum += __fdividef(inter, area_p + area_g - inter + 1e-7f);
        }
    }

    // intra-warp reduce
    #pragma unroll
    for (int off = 16; off > 0; off >>= 1) {
        iou_sum += __shfl_down_sync(0xFFFFFFFFu, iou_sum, off);
        mse_sum += __shfl_down_sync(0xFFFFFFFFu, mse_sum, off);
        n_inc   += __shfl_down_sync(0xFFFFFFFFu, n_inc, off);
    }

    __shared__ float s_iou[8];
    __shared__ float s_mse[8];
    __shared__ unsigned int s_ni[8];
    __shared__ bool s_last;
    const int wid = threadIdx.x >> 5;
    const int lid = threadIdx.x & 31;
    if (lid == 0) {
        s_iou[wid] = iou_sum;
        s_mse[wid] = mse_sum;
        s_ni[wid] = n_inc;
    }
    __syncthreads();
    if (threadIdx.x == 0) {
        float biou = 0.0f, bmse = 0.0f;
        unsigned int bni = 0u;
        #pragma unroll
        for (int w = 0; w < NTHREADS / 32; w++) {
            biou += s_iou[w];
            bmse += s_mse[w];
            bni += s_ni[w];
        }
        g_p_iou[blockIdx.x] = biou;
        g_p_mse[blockIdx.x] = bmse;
        g_p_ni[blockIdx.x] = bni;
        __threadfence();
        const unsigned int old = atomicAdd(&g_ticket, 1u);
        s_last = (old == gridDim.x - 1u);
    }
    __syncthreads();

    if (s_last) {
        // Last block reduces all per-block partials and finalizes.
        double diou = 0.0, dmse = 0.0;
        unsigned long long dni = 0ull;
        for (int b = threadIdx.x; b < (int)gridDim.x; b += NTHREADS) {
            diou += (double)g_p_iou[b];
            dmse += (double)g_p_mse[b];
            dni += (unsigned long long)g_p_ni[b];
        }
        #pragma unroll
        for (int off = 16; off > 0; off >>= 1) {
            diou += __shfl_down_sync(0xFFFFFFFFu, diou, off);
            dmse += __shfl_down_sync(0xFFFFFFFFu, dmse, off);
            dni  += __shfl_down_sync(0xFFFFFFFFu, dni, off);
        }
        __shared__ double f_iou[8];
        __shared__ double f_mse[8];
        __shared__ unsigned long long f_ni[8];
        if (lid == 0) {
            f_iou[wid] = diou;
            f_mse[wid] = dmse;
            f_ni[wid] = dni;
        }
        __syncthreads();
        if (threadIdx.x == 0) {
            double tiou = 0.0, tmse = 0.0;
            unsigned long long tni = 0ull;
            #pragma unroll
            for (int w = 0; w < NTHREADS / 32; w++) {
                tiou += f_iou[w];
                tmse += f_mse[w];
                tni += f_ni[w];
            }
            const unsigned long long tnc = (unsigned long long)n - tni;
            const double mse_denom = (double)((tni > 0ull) ? tni * 4ull : 1ull);
            const double iou_denom = (double)((tnc > 0ull) ? tnc : 1ull);
            const float mse_mean = (float)(tmse / mse_denom);
            const float iou_mean = (float)(tiou / iou_denom);
            float res_full = iou_mean + ((tni > 0ull) ? -mse_mean : 0.0f);
            out[0] = (tnc > 0ull) ? res_full : -mse_mean;
            g_ticket = 0u;  // reset for next graph replay
        }
    }
}

extern "C" void kernel_launch(void* const* d_in, const int* in_sizes, int n_in,
                              void* d_out, int out_size) {
    const float4* pr = (const float4*)d_in[0];
    const float4* gt = (const float4*)d_in[1];
    float* out = (float*)d_out;
    const int n = in_sizes[0] / 4;

    iou_dots_fused<<<NBLOCKS, NTHREADS>>>(pr, gt, out, n);
}

// round 9
// speedup vs baseline: 1.1934x; 1.0416x over previous
#include <cuda_runtime.h>
#include <cuda_bf16.h>

#define NBLOCKS 2368
#define NTHREADS 256

// Per-block partials: every slot written each run -> no init kernel needed.
__device__ float g_p_iou[NBLOCKS];
__device__ float g_p_mse[NBLOCKS];
__device__ unsigned int g_p_ni[NBLOCKS];
// Ticket counter: statically 0; last block resets it -> graph-replay safe.
__device__ unsigned int g_ticket = 0;

__device__ __forceinline__ void process_box(const float4 p, const float4 g,
                                            float& iou_sum, float& mse_sum,
                                            unsigned int& n_inc) {
    // gt corners (cx,cy,w,h -> xyxy)
    const float x_min_t = g.x - g.z * 0.5f;
    const float x_max_t = g.x + g.z * 0.5f;
    const float y_min_t = g.y - g.w * 0.5f;
    const float y_max_t = g.y + g.w * 0.5f;
    // pred corners clipped to [0,1]
    const float x_min_p = fmaxf(p.x - p.z * 0.5f, 0.0f);
    const float x_max_p = fminf(p.x + p.z * 0.5f, 1.0f);
    const float y_min_p = fmaxf(p.y - p.w * 0.5f, 0.0f);
    const float y_max_p = fminf(p.y + p.w * 0.5f, 1.0f);
    // overlap box
    const float o0 = fmaxf(x_min_t, x_min_p);
    const float o1 = fmaxf(y_min_t, y_min_p);
    const float o2 = fminf(x_max_t, x_max_p);
    const float o3 = fminf(y_max_t, y_max_p);

    const bool inc = (o2 < o0) || (o3 < o1);

    // Branchless: compute both contributions, select.
    const float dx = p.x - g.x;
    const float dy = p.y - g.y;
    const float dz = p.z - g.z;
    const float dw = p.w - g.w;
    const float sq = dx * dx + dy * dy + dz * dz + dw * dw;

    const float inter = (o2 - o0) * (o3 - o1);
    const float area_p = p.z * p.w;
    const float area_g = g.z * g.w;
    const float iou = __fdividef(inter, area_p + area_g - inter + 1e-7f);

    mse_sum += inc ? sq : 0.0f;
    iou_sum += inc ? 0.0f : iou;
    n_inc += inc ? 1u : 0u;
}

__global__ void __launch_bounds__(NTHREADS) iou_dots_fused(
    const float4* __restrict__ pr,
    const float4* __restrict__ gt,
    float* __restrict__ out,
    int n)
{
    float iou_sum = 0.0f;
    float mse_sum = 0.0f;
    unsigned int n_inc = 0u;

    const int stride = gridDim.x * blockDim.x;
    int i = blockIdx.x * blockDim.x + threadIdx.x;

    // x2 unroll: 4 independent LDG.128 in flight before any compute.
    for (; i + stride < n; i += 2 * stride) {
        const float4 p0 = pr[i];
        const float4 g0 = gt[i];
        const float4 p1 = pr[i + stride];
        const float4 g1 = gt[i + stride];
        process_box(p0, g0, iou_sum, mse_sum, n_inc);
        process_box(p1, g1, iou_sum, mse_sum, n_inc);
    }
    if (i < n) {
        process_box(pr[i], gt[i], iou_sum, mse_sum, n_inc);
    }

    // intra-warp reduce
    #pragma unroll
    for (int off = 16; off > 0; off >>= 1) {
        iou_sum += __shfl_down_sync(0xFFFFFFFFu, iou_sum, off);
        mse_sum += __shfl_down_sync(0xFFFFFFFFu, mse_sum, off);
        n_inc   += __shfl_down_sync(0xFFFFFFFFu, n_inc, off);
    }

    __shared__ float s_iou[8];
    __shared__ float s_mse[8];
    __shared__ unsigned int s_ni[8];
    __shared__ bool s_last;
    const int wid = threadIdx.x >> 5;
    const int lid = threadIdx.x & 31;
    if (lid == 0) {
        s_iou[wid] = iou_sum;
        s_mse[wid] = mse_sum;
        s_ni[wid] = n_inc;
    }
    __syncthreads();
    if (threadIdx.x == 0) {
        float biou = 0.0f, bmse = 0.0f;
        unsigned int bni = 0u;
        #pragma unroll
        for (int w = 0; w < NTHREADS / 32; w++) {
            biou += s_iou[w];
            bmse += s_mse[w];
            bni += s_ni[w];
        }
        g_p_iou[blockIdx.x] = biou;
        g_p_mse[blockIdx.x] = bmse;
        g_p_ni[blockIdx.x] = bni;
        __threadfence();
        const unsigned int old = atomicAdd(&g_ticket, 1u);
        s_last = (old == gridDim.x - 1u);
    }
    __syncthreads();

    if (s_last) {
        // Last block reduces all per-block partials and finalizes.
        double diou = 0.0, dmse = 0.0;
        unsigned long long dni = 0ull;
        for (int b = threadIdx.x; b < (int)gridDim.x; b += NTHREADS) {
            diou += (double)g_p_iou[b];
            dmse += (double)g_p_mse[b];
            dni += (unsigned long long)g_p_ni[b];
        }
        #pragma unroll
        for (int off = 16; off > 0; off >>= 1) {
            diou += __shfl_down_sync(0xFFFFFFFFu, diou, off);
            dmse += __shfl_down_sync(0xFFFFFFFFu, dmse, off);
            dni  += __shfl_down_sync(0xFFFFFFFFu, dni, off);
        }
        __shared__ double f_iou[8];
        __shared__ double f_mse[8];
        __shared__ unsigned long long f_ni[8];
        if (lid == 0) {
            f_iou[wid] = diou;
            f_mse[wid] = dmse;
            f_ni[wid] = dni;
        }
        __syncthreads();
        if (threadIdx.x == 0) {
            double tiou = 0.0, tmse = 0.0;
            unsigned long long tni = 0ull;
            #pragma unroll
            for (int w = 0; w < NTHREADS / 32; w++) {
                tiou += f_iou[w];
                tmse += f_mse[w];
                tni += f_ni[w];
            }
            const unsigned long long tnc = (unsigned long long)n - tni;
            const double mse_denom = (double)((tni > 0ull) ? tni * 4ull : 1ull);
            const double iou_denom = (double)((tnc > 0ull) ? tnc : 1ull);
            const float mse_mean = (float)(tmse / mse_denom);
            const float iou_mean = (float)(tiou / iou_denom);
            float res_full = iou_mean + ((tni > 0ull) ? -mse_mean : 0.0f);
            out[0] = (tnc > 0ull) ? res_full : -mse_mean;
            g_ticket = 0u;  // reset for next graph replay
        }
    }
}

extern "C" void kernel_launch(void* const* d_in, const int* in_sizes, int n_in,
                              void* d_out, int out_size) {
    const float4* pr = (const float4*)d_in[0];
    const float4* gt = (const float4*)d_in[1];
    float* out = (float*)d_out;
    const int n = in_sizes[0] / 4;

    iou_dots_fused<<<NBLOCKS, NTHREADS>>>(pr, gt, out, n);
}